// round 5
// baseline (speedup 1.0000x reference)
#include <cuda_runtime.h>
#include <cstdint>
#include <cstddef>

// ---------------------------------------------------------------------------
// WITRAN 2D-PSGMU encoder.
// input: (B=32, rows=48, cols=24, C=32) fp32
// W:     (1536, 544) fp32   (rows = [u_row|o_row|u_col|o_col|i_row|i_col] x 256)
// Bp:    (1536,) fp32
// Outputs (concatenated into d_out, fp32):
//   output_all     (768, 71, 512)   = 27,906,048
//   hidden_col_all (32, 1, 48, 256) =    393,216
//   hidden_row_all (32, 1, 24, 256) =    196,608
// ---------------------------------------------------------------------------

#define BATCH 32
#define RCOL  24
#define LROW  48
#define LTOT  71          // RCOL + LROW - 1
#define NJ    768         // RCOL * BATCH
#define HID   256
#define CIN   32
#define KDIM  544         // 2*HID + CIN
#define KT    16          // K tile
#define NKT   34          // KDIM / KT
#define WS_STRIDE 193     // padded smem stride for W tile (conflict-free STS/LDS)
#define THREADS 256

// Recurrent state, ping-pong buffers (double-buffered: different column-tile
// CTAs write the next state while others still read the current one).
__device__ float g_hrow[2][NJ * HID];
__device__ float g_hcol[2][NJ * HID];

__global__ void witran_init()
{
    int idx = blockIdx.x * blockDim.x + threadIdx.x;
    if (idx < NJ * HID) {
        g_hrow[0][idx] = 0.f;
        g_hcol[0][idx] = 0.f;
    }
}

__device__ __forceinline__ unsigned smem_u32(const void* p)
{
    return (unsigned)__cvta_generic_to_shared(p);
}

// 4-byte cp.async with zero-fill predicate (src_size = 0 -> zero fill)
__device__ __forceinline__ void cp4(unsigned dst, const float* src, int sz)
{
    asm volatile("cp.async.ca.shared.global [%0], [%1], 4, %2;"
                 :: "r"(dst), "l"(src), "r"(sz) : "memory");
}
__device__ __forceinline__ void cp_commit()
{
    asm volatile("cp.async.commit_group;" ::: "memory");
}

__device__ __forceinline__ float sigmoid_f(float x)
{
    // robust: x->-inf gives 1/(1+inf)=0; x->+inf gives 1/(1+0)=1
    return __fdividef(1.f, 1.f + __expf(-x));
}
__device__ __forceinline__ float tanh_f(float x)
{
    float ax = fabsf(x);
    float e  = __expf(-2.f * ax);           // in (0,1], never overflows
    float t  = __fdividef(1.f - e, 1.f + e);
    return copysignf(t, x);
}

// One recurrence step.
// Grid: 128 CTAs = 16 row-tiles (48 rows) x 8 col-tiles (32 hidden units x 6 gates).
// Thread (256): nl = tid&31 -> hidden unit lane; jg = tid>>5 -> 6-row group.
// Micro-tile per thread: 6 rows x 6 gates of one hidden unit -> epilogue is
// fully thread-local (all six gates of unit n are in this thread's accumulators).
__global__ __launch_bounds__(THREADS, 1)
void witran_step(const float* __restrict__ inp,
                 const float* __restrict__ Wg,
                 const float* __restrict__ Bp,
                 float* __restrict__ out0,
                 float* __restrict__ out1,
                 float* __restrict__ out2,
                 int s)
{
    __shared__ __align__(16) float Zs[2][LROW * KT];        // [buf][j*16 + k]
    __shared__ __align__(16) float Ws[2][KT * WS_STRIDE];   // [buf][k*193 + t*32 + n]

    const int tid = threadIdx.x;
    const int nt  = blockIdx.x & 7;    // column tile (hidden units)
    const int mt  = blockIdx.x >> 3;   // row tile
    const int j0  = mt * 48;
    const int n0  = nt * 32;

    const int cur = s & 1;
    const int nxt = cur ^ 1;
    const float* hrow_cur = g_hrow[cur];
    const float* hcol_cur = g_hcol[cur];
    float* hrow_nxt = g_hrow[nxt];
    float* hcol_nxt = g_hcol[nxt];

    float acc[36];
#pragma unroll
    for (int i = 0; i < 36; i++) acc[i] = 0.f;

    const int nl  = tid & 31;
    const int jg  = tid >> 5;
    const int jr0 = jg * 6;

    // loader lane mapping
    const int kk = tid & 15;   // k offset within tile
    const int qg = tid >> 4;   // 0..15

    auto stage = [&](int kt, int buf) {
        const int k0 = kt * KT;
        // --- W tile: 192 gate-rows x 16 k, 12 elements/thread ---
        unsigned wbase = smem_u32(&Ws[buf][kk * WS_STRIDE]);
        const float* wsrc0 = Wg + k0 + kk;
#pragma unroll
        for (int i = 0; i < 12; i++) {
            int q = qg * 12 + i;           // q = t*32 + n_local
            int t = q >> 5, n = q & 31;
            cp4(wbase + q * 4, wsrc0 + (size_t)(t * 256 + n0 + n) * KDIM, 4);
        }
        // --- Z tile: 48 rows x 16 k, 3 elements/thread ---
#pragma unroll
        for (int i = 0; i < 3; i++) {
            int jl = qg * 3 + i;
            int j  = j0 + jl;
            unsigned dst = smem_u32(&Zs[buf][jl * KT + kk]);
            const float* src;
            int sz = 4;
            if (k0 < 256) {
                src = hrow_cur + (size_t)j * HID + k0 + kk;
            } else if (k0 < 512) {
                src = hcol_cur + (size_t)j * HID + (k0 - 256) + kk;
            } else {
                int r = j >> 5, b = j & 31, row = s - r;
                if (row >= 0 && row < LROW)
                    src = inp + ((size_t)((b * LROW + row) * RCOL + r)) * CIN
                              + (k0 - 512) + kk;
                else { src = inp; sz = 0; }   // zero-fill (outside valid window)
            }
            cp4(dst, src, sz);
        }
        cp_commit();
    };

    stage(0, 0);

    for (int kt = 0; kt < NKT; kt++) {
        const int buf = kt & 1;
        if (kt + 1 < NKT) {
            stage(kt + 1, buf ^ 1);
            asm volatile("cp.async.wait_group 1;" ::: "memory");
        } else {
            asm volatile("cp.async.wait_group 0;" ::: "memory");
        }
        __syncthreads();

        const float* Zb = Zs[buf];
        const float* Wb = Ws[buf];
#pragma unroll
        for (int q4 = 0; q4 < 4; q4++) {
            float4 z[6];
#pragma unroll
            for (int jj = 0; jj < 6; jj++)
                z[jj] = *reinterpret_cast<const float4*>(&Zb[(jr0 + jj) * KT + q4 * 4]);
#pragma unroll
            for (int kq = 0; kq < 4; kq++) {
                float w[6];
#pragma unroll
                for (int t = 0; t < 6; t++)
                    w[t] = Wb[(q4 * 4 + kq) * WS_STRIDE + t * 32 + nl];
#pragma unroll
                for (int jj = 0; jj < 6; jj++) {
                    float zv = (kq == 0) ? z[jj].x : (kq == 1) ? z[jj].y
                             : (kq == 2) ? z[jj].z : z[jj].w;
#pragma unroll
                    for (int t = 0; t < 6; t++)
                        acc[jj * 6 + t] = fmaf(zv, w[t], acc[jj * 6 + t]);
                }
            }
        }
        __syncthreads();
    }

    // ---------------- epilogue: gates, state update, outputs ----------------
    const int n = n0 + nl;
    float bp[6];
#pragma unroll
    for (int t = 0; t < 6; t++) bp[t] = Bp[t * 256 + n];

#pragma unroll
    for (int jj = 0; jj < 6; jj++) {
        int j = j0 + jr0 + jj;
        int r = j >> 5;
        float m = (r <= s && s < RCOL) ? 1.f : 0.f;

        float u_row = sigmoid_f(acc[jj * 6 + 0] + m * bp[0]);
        float o_row = sigmoid_f(acc[jj * 6 + 1] + m * bp[1]);
        float u_col = sigmoid_f(acc[jj * 6 + 2] + m * bp[2]);
        float o_col = sigmoid_f(acc[jj * 6 + 3] + m * bp[3]);
        float i_row = tanh_f   (acc[jj * 6 + 4] + m * bp[4]);
        float i_col = tanh_f   (acc[jj * 6 + 5] + m * bp[5]);

        float hro = hrow_cur[(size_t)j * HID + n];
        float hco = hcol_cur[(size_t)j * HID + n];

        // (1-u)*h + u*i  ==  h + u*(i - h)
        float hr = tanh_f(fmaf(u_row, i_row - hro, hro)) * o_row;
        float hc = tanh_f(fmaf(u_col, i_col - hco, hco)) * o_col;

        hrow_nxt[(size_t)j * HID + n] = hr;
        int j2 = j + BATCH; if (j2 >= NJ) j2 -= NJ;     // roll by B
        hcol_nxt[(size_t)j2 * HID + n] = hc;

        size_t ob = ((size_t)j * LTOT + s) * (2 * HID);
        out0[ob + n]       = hr;
        out0[ob + HID + n] = hc;

        if (r == RCOL - 1 && s >= RCOL - 1)
            out1[((size_t)(j & 31) * LROW + (s - (RCOL - 1))) * HID + n] = hc;
        if (s - r == LROW - 1)
            out2[((size_t)(j & 31) * RCOL + r) * HID + n] = hr;
    }
}

extern "C" void kernel_launch(void* const* d_in, const int* in_sizes, int n_in,
                              void* d_out, int out_size)
{
    const float* inp = (const float*)d_in[0];   // (32,48,24,32)
    const float* Wg  = (const float*)d_in[1];   // (1536,544)
    const float* Bp  = (const float*)d_in[2];   // (1536,)

    float* out0 = (float*)d_out;                              // (768,71,512)
    float* out1 = out0 + (size_t)NJ * LTOT * (2 * HID);       // (32,48,256)
    float* out2 = out1 + (size_t)BATCH * LROW * HID;          // (32,24,256)

    witran_init<<<(NJ * HID + 255) / 256, 256>>>();
    for (int s = 0; s < LTOT; s++) {
        witran_step<<<128, THREADS>>>(inp, Wg, Bp, out0, out1, out2, s);
    }
    (void)in_sizes; (void)n_in; (void)out_size;
}

// round 10
// speedup vs baseline: 1.0453x; 1.0453x over previous
#include <cuda_runtime.h>
#include <cstdint>
#include <cstddef>

// ---------------------------------------------------------------------------
// WITRAN 2D-PSGMU encoder — packed-fp32 (FFMA2) recurrent GEMM version.
// input: (B=32, rows=48, cols=24, C=32) fp32
// W:     (1536, 544) fp32   (rows = [u_row|o_row|u_col|o_col|i_row|i_col] x 256)
// Bp:    (1536,) fp32
// Outputs (concatenated into d_out, fp32):
//   output_all     (768, 71, 512), hidden_col_all (32,1,48,256),
//   hidden_row_all (32,1,24,256)
// ---------------------------------------------------------------------------

#define BATCH 32
#define RCOL  24
#define LROW  48
#define LTOT  71          // RCOL + LROW - 1
#define NJ    768         // RCOL * BATCH
#define HID   256
#define CIN   32
#define KDIM  544         // 2*HID + CIN
#define KT    16          // K tile
#define NKT   34          // KDIM / KT
#define WSTR  194         // padded word stride per k-row of W tile (even: 8B align)
#define THREADS 256

// Recurrent state, ping-pong buffers.
__device__ float g_hrow[2][NJ * HID];
__device__ float g_hcol[2][NJ * HID];

__global__ void witran_init()
{
    int idx = blockIdx.x * blockDim.x + threadIdx.x;
    if (idx < NJ * HID) {
        g_hrow[0][idx] = 0.f;
        g_hcol[0][idx] = 0.f;
    }
}

__device__ __forceinline__ unsigned smem_u32(const void* p)
{
    return (unsigned)__cvta_generic_to_shared(p);
}

__device__ __forceinline__ void cp4(unsigned dst, const float* src, int sz)
{
    asm volatile("cp.async.ca.shared.global [%0], [%1], 4, %2;"
                 :: "r"(dst), "l"(src), "r"(sz) : "memory");
}
__device__ __forceinline__ void cp_commit()
{
    asm volatile("cp.async.commit_group;" ::: "memory");
}

__device__ __forceinline__ unsigned long long pack2(float x)
{
    unsigned long long r;
    asm("mov.b64 %0, {%1, %1};" : "=l"(r) : "f"(x));
    return r;
}
__device__ __forceinline__ void fma2(unsigned long long& d,
                                     unsigned long long a,
                                     unsigned long long b)
{
    asm("fma.rn.f32x2 %0, %1, %2, %0;" : "+l"(d) : "l"(a), "l"(b));
}
__device__ __forceinline__ void unpack2(unsigned long long v, float& lo, float& hi)
{
    asm("mov.b64 {%0, %1}, %2;" : "=f"(lo), "=f"(hi) : "l"(v));
}

__device__ __forceinline__ float sigmoid_f(float x)
{
    return __fdividef(1.f, 1.f + __expf(-x));
}
__device__ __forceinline__ float tanh_f(float x)
{
    float ax = fabsf(x);
    float e  = __expf(-2.f * ax);
    float t  = __fdividef(1.f - e, 1.f + e);
    return copysignf(t, x);
}

// One recurrence step.
// Grid: 128 CTAs = 16 row-tiles (48 rows) x 8 col-tiles (32 hidden units).
// Thread mapping: nlh = tid&15 -> hidden unit pair (n0+nlh, n0+nlh+16);
//                 jg  = tid>>4 -> 3-row group.
// Micro-tile per thread: 3 rows x 2 units x 6 gates, packed as f32x2 over the
// unit pair -> 18 FFMA2 per k. Epilogue fully thread-local.
__global__ __launch_bounds__(THREADS, 1)
void witran_step(const float* __restrict__ inp,
                 const float* __restrict__ Wg,
                 const float* __restrict__ Bp,
                 float* __restrict__ out0,
                 float* __restrict__ out1,
                 float* __restrict__ out2,
                 int s)
{
    __shared__ __align__(16) float Zs[3][LROW * KT];   // [buf][jl*16 + k]
    __shared__ __align__(16) float Ws[3][KT * WSTR];   // [buf][k*194 + q], q=t*32+nlh*2+half

    const int tid = threadIdx.x;
    const int nt  = blockIdx.x & 7;
    const int mt  = blockIdx.x >> 3;
    const int j0  = mt * 48;
    const int n0  = nt * 32;

    const int cur = s & 1;
    const int nxt = cur ^ 1;
    const float* hrow_cur = g_hrow[cur];
    const float* hcol_cur = g_hcol[cur];
    float* hrow_nxt = g_hrow[nxt];
    float* hcol_nxt = g_hcol[nxt];

    unsigned long long acc[3][6];
#pragma unroll
    for (int p = 0; p < 3; p++)
#pragma unroll
        for (int t = 0; t < 6; t++) acc[p][t] = 0ull;

    const int nlh = tid & 15;
    const int jg  = tid >> 4;
    const int jr0 = jg * 3;

    // loader lane mapping
    const int kk = tid & 15;
    const int qg = tid >> 4;

    auto stage = [&](int kt, int buf) {
        const int k0 = kt * KT;
        // --- W tile: 192 elements per k (6 gates x 32 units, pair-interleaved),
        //     12 elements/thread. dst word q = t*32 + nlh*2 + half. ---
        unsigned wbase = smem_u32(&Ws[buf][kk * WSTR]);
        const float* wsrc0 = Wg + k0 + kk;
#pragma unroll
        for (int i = 0; i < 12; i++) {
            int q    = qg * 12 + i;
            int t    = q >> 5;
            int unit = ((q >> 1) & 15) + ((q & 1) << 4);
            cp4(wbase + q * 4, wsrc0 + (size_t)(t * 256 + n0 + unit) * KDIM, 4);
        }
        // --- Z tile: 48 rows x 16 k, 3 elements/thread ---
#pragma unroll
        for (int i = 0; i < 3; i++) {
            int jl = qg * 3 + i;
            int j  = j0 + jl;
            unsigned dst = smem_u32(&Zs[buf][jl * KT + kk]);
            const float* src;
            int sz = 4;
            if (k0 < 256) {
                src = hrow_cur + (size_t)j * HID + k0 + kk;
            } else if (k0 < 512) {
                src = hcol_cur + (size_t)j * HID + (k0 - 256) + kk;
            } else {
                int r = j >> 5, b = j & 31, row = s - r;
                if (row >= 0 && row < LROW)
                    src = inp + ((size_t)((b * LROW + row) * RCOL + r)) * CIN
                              + (k0 - 512) + kk;
                else { src = inp; sz = 0; }   // zero-fill outside valid window
            }
            cp4(dst, src, sz);
        }
        cp_commit();
    };

    stage(0, 0);
    stage(1, 1);

    int buf = 0;
    for (int kt = 0; kt < NKT; kt++) {
        if (kt < NKT - 1)
            asm volatile("cp.async.wait_group 1;" ::: "memory");
        else
            asm volatile("cp.async.wait_group 0;" ::: "memory");
        __syncthreads();

        if (kt + 2 < NKT) {
            int nb = buf + 2; if (nb >= 3) nb -= 3;
            stage(kt + 2, nb);
        }

        const float* Zb = &Zs[buf][0];
        const float* Wbase = &Ws[buf][0];
#pragma unroll
        for (int k = 0; k < KT; k++) {
            unsigned long long zz0 = pack2(Zb[(jr0 + 0) * KT + k]);
            unsigned long long zz1 = pack2(Zb[(jr0 + 1) * KT + k]);
            unsigned long long zz2 = pack2(Zb[(jr0 + 2) * KT + k]);
            const unsigned long long* Wrow =
                reinterpret_cast<const unsigned long long*>(Wbase + k * WSTR);
#pragma unroll
            for (int t = 0; t < 6; t++) {
                unsigned long long w = Wrow[t * 16 + nlh];
                fma2(acc[0][t], zz0, w);
                fma2(acc[1][t], zz1, w);
                fma2(acc[2][t], zz2, w);
            }
        }
        buf++; if (buf == 3) buf = 0;
    }

    // ---------------- epilogue: gates, state update, outputs ----------------
    const int nA = n0 + nlh;
    const int nB = nA + 16;
    float bp[6][2];
#pragma unroll
    for (int t = 0; t < 6; t++) {
        bp[t][0] = Bp[t * 256 + nA];
        bp[t][1] = Bp[t * 256 + nB];
    }

#pragma unroll
    for (int jj = 0; jj < 3; jj++) {
        int j = j0 + jr0 + jj;
        int r = j >> 5;
        float m = (r <= s && s < RCOL) ? 1.f : 0.f;

        float g[6][2];
#pragma unroll
        for (int t = 0; t < 6; t++) unpack2(acc[jj][t], g[t][0], g[t][1]);

        int j2 = j + BATCH; if (j2 >= NJ) j2 -= NJ;     // roll by B
        size_t ob = ((size_t)j * LTOT + s) * (2 * HID);

#pragma unroll
        for (int h = 0; h < 2; h++) {
            int n = (h == 0) ? nA : nB;

            float u_row = sigmoid_f(g[0][h] + m * bp[0][h]);
            float o_row = sigmoid_f(g[1][h] + m * bp[1][h]);
            float u_col = sigmoid_f(g[2][h] + m * bp[2][h]);
            float o_col = sigmoid_f(g[3][h] + m * bp[3][h]);
            float i_row = tanh_f   (g[4][h] + m * bp[4][h]);
            float i_col = tanh_f   (g[5][h] + m * bp[5][h]);

            float hro = hrow_cur[(size_t)j * HID + n];
            float hco = hcol_cur[(size_t)j * HID + n];

            float hr = tanh_f(fmaf(u_row, i_row - hro, hro)) * o_row;
            float hc = tanh_f(fmaf(u_col, i_col - hco, hco)) * o_col;

            hrow_nxt[(size_t)j * HID + n]  = hr;
            hcol_nxt[(size_t)j2 * HID + n] = hc;

            out0[ob + n]       = hr;
            out0[ob + HID + n] = hc;

            if (r == RCOL - 1 && s >= RCOL - 1)
                out1[((size_t)(j & 31) * LROW + (s - (RCOL - 1))) * HID + n] = hc;
            if (s - r == LROW - 1)
                out2[((size_t)(j & 31) * RCOL + r) * HID + n] = hr;
        }
    }
}

extern "C" void kernel_launch(void* const* d_in, const int* in_sizes, int n_in,
                              void* d_out, int out_size)
{
    const float* inp = (const float*)d_in[0];   // (32,48,24,32)
    const float* Wg  = (const float*)d_in[1];   // (1536,544)
    const float* Bp  = (const float*)d_in[2];   // (1536,)

    float* out0 = (float*)d_out;                              // (768,71,512)
    float* out1 = out0 + (size_t)NJ * LTOT * (2 * HID);       // (32,48,256)
    float* out2 = out1 + (size_t)BATCH * LROW * HID;          // (32,24,256)

    witran_init<<<(NJ * HID + 255) / 256, 256>>>();
    for (int s = 0; s < LTOT; s++) {
        witran_step<<<128, THREADS>>>(inp, Wg, Bp, out0, out1, out2, s);
    }
    (void)in_sizes; (void)n_in; (void)out_size;
}